// round 8
// baseline (speedup 1.0000x reference)
#include <cuda_runtime.h>
#include <cstdint>

#define N_ATOMS 4096
#define L_WORDS 65536
#define DD 10
#define KS 23
#define KSPLIT 2
#define KCHUNK (N_ATOMS / KSPLIT)   // 2048
#define NT 256
#define SMEM_BYTES 81920            // 40 * (KCHUNK/8) * 8 = 80KB
#define MVROWS 8                    // rows/warp, bf16 mv (layers 1,2)
#define MVTILE 64

typedef unsigned long long ull;

// ---------------- scratch (device globals; no allocation allowed) ----------
__device__ float g_xs[N_ATOMS * DD];
__device__ ull   g_hs[8 * 5 * (N_ATOMS / 8)];        // hs f32x2, [k8][p][m/8]
__device__ uint4 g_Ab[(size_t)N_ATOMS * N_ATOMS / 8];// A bf16 (written by layer0)
__device__ float g_pp[KSPLIT][N_ATOMS * DD];
__device__ float g_cnn[2][L_WORDS * DD];
__device__ float g_comp[DD];
__device__ float g_cpart[512 * DD];
__device__ float g_part[512 * DD];
__device__ unsigned g_bar;

// ---------------- helpers ------------------------------------------------------
__device__ __forceinline__ ull pack2(float x, float y) {
    ull r; asm("mov.b64 %0, {%1, %2};" : "=l"(r) : "f"(x), "f"(y)); return r;
}
__device__ __forceinline__ void unpack2(ull v, float& x, float& y) {
    asm("mov.b64 {%0, %1}, %2;" : "=f"(x), "=f"(y) : "l"(v));
}
__device__ __forceinline__ void fma2(ull& d, ull a, ull b) {
    asm("fma.rn.f32x2 %0, %1, %2, %0;" : "+l"(d) : "l"(a), "l"(b));
}
__device__ __forceinline__ unsigned bfpack(float lo, float hi) {
    unsigned r;
    asm("cvt.rn.bf16x2.f32 %0, %1, %2;" : "=r"(r) : "f"(hi), "f"(lo));
    return r;
}

// ---------------- grid barrier (monotonic; replay-safe) ------------------------
__device__ __forceinline__ void gbar() {
    __syncthreads();
    if (threadIdx.x == 0) {
        __threadfence();
        unsigned old = atomicAdd(&g_bar, 1u);
        unsigned target = (old / gridDim.x + 1u) * gridDim.x;
        while (*(volatile unsigned*)&g_bar < target) { }
    }
    __syncthreads();
    __threadfence();
}

// ---------------- hs for one atom ------------------------------------------------
__device__ __forceinline__ void hs_store(int m, const float* x,
                                         const float* Wgl, const float* bgl) {
    int k8 = m & 7, base = m >> 3;
#pragma unroll
    for (int p = 0; p < 5; p++) {
        float h0 = bgl[2 * p], h1 = bgl[2 * p + 1];
#pragma unroll
        for (int c = 0; c < DD; c++) {
            h0 = fmaf(x[c], Wgl[(2 * p) * DD + c], h0);
            h1 = fmaf(x[c], Wgl[(2 * p + 1) * DD + c], h1);
        }
        g_hs[(k8 * 5 + p) * (N_ATOMS / 8) + base] =
            pack2(fmaxf(h0, 0.f), fmaxf(h1, 0.f));
    }
}

// ---- smem hs-chunk fill (shared by both mv variants) ---------------------------
__device__ __forceinline__ void fill_hs(ull* sh, int kb) {
    for (int i = threadIdx.x; i < 40 * (KCHUNK / 8); i += NT) {
        int kp = i / (KCHUNK / 8), j = i % (KCHUNK / 8);
        sh[i] = g_hs[kp * (N_ATOMS / 8) + kb * (KCHUNK / 8) + j];
    }
    __syncthreads();
}

// ---------------- layer-0 mv tile: fp32 A read + bf16 write, 32 rows ------------
__device__ __forceinline__ void mv0_tile(char* smem_raw, int u, const float* A) {
    ull* sh = (ull*)smem_raw;
    const int tid = threadIdx.x;
    const int rowblk = u & 127, kb = u >> 7;
    fill_hs(sh, kb);

    const int warp = tid >> 5, lane = tid & 31;
    const int row0 = rowblk * 32 + warp * 4;
    float* pout = g_pp[kb];

    const float4* Af[4];
    uint4* Ao[4];
#pragma unroll
    for (int r = 0; r < 4; r++) {
        Af[r] = (const float4*)A + (size_t)(row0 + r) * (N_ATOMS / 4) + kb * (KCHUNK / 4);
        Ao[r] = g_Ab + (size_t)(row0 + r) * (N_ATOMS / 8) + kb * (KCHUNK / 8);
    }

    ull acc[4][5];
#pragma unroll
    for (int r = 0; r < 4; r++)
#pragma unroll
        for (int p = 0; p < 5; p++) acc[r][p] = 0ull;

    for (int it = 0; it < KCHUNK / 256; it++) {
        int q = it * 32 + lane;         // 8-col group index, 0..255
        float4 lo[4], hi[4];
#pragma unroll
        for (int r = 0; r < 4; r++) {
            lo[r] = Af[r][2 * q];
            hi[r] = Af[r][2 * q + 1];
            uint4 o;
            o.x = bfpack(lo[r].x, lo[r].y);
            o.y = bfpack(lo[r].z, lo[r].w);
            o.z = bfpack(hi[r].x, hi[r].y);
            o.w = bfpack(hi[r].z, hi[r].w);
            Ao[r][q] = o;
        }
#pragma unroll
        for (int k8 = 0; k8 < 8; k8++) {
            ull h[5];
#pragma unroll
            for (int p = 0; p < 5; p++)
                h[p] = sh[(k8 * 5 + p) * (KCHUNK / 8) + q];
#pragma unroll
            for (int r = 0; r < 4; r++) {
                float av = (k8 == 0) ? lo[r].x : (k8 == 1) ? lo[r].y
                         : (k8 == 2) ? lo[r].z : (k8 == 3) ? lo[r].w
                         : (k8 == 4) ? hi[r].x : (k8 == 5) ? hi[r].y
                         : (k8 == 6) ? hi[r].z : hi[r].w;
                ull v = pack2(av, av);
#pragma unroll
                for (int p = 0; p < 5; p++) fma2(acc[r][p], v, h[p]);
            }
        }
    }

#pragma unroll
    for (int r = 0; r < 4; r++) {
        float f[DD];
#pragma unroll
        for (int p = 0; p < 5; p++) unpack2(acc[r][p], f[2 * p], f[2 * p + 1]);
#pragma unroll
        for (int d = 0; d < DD; d++)
#pragma unroll
            for (int o = 16; o > 0; o >>= 1)
                f[d] += __shfl_down_sync(0xffffffffu, f[d], o);
        if (lane == 0)
#pragma unroll
            for (int d = 0; d < DD; d++) pout[(row0 + r) * DD + d] = f[d];
    }
}

// ---------------- bf16 mv tile (layers 1,2): 64 rows ---------------------------
__device__ __forceinline__ void mv_tile(char* smem_raw, int u) {
    ull* sh = (ull*)smem_raw;
    const int tid = threadIdx.x;
    const int rowblk = u & 63, kb = u >> 6;
    fill_hs(sh, kb);

    const int warp = tid >> 5, lane = tid & 31;
    const int row0 = rowblk * MVTILE + warp * MVROWS;
    float* pout = g_pp[kb];
    const int rstride = N_ATOMS / 8;
    const uint4* Abase = g_Ab + (size_t)row0 * rstride + kb * (KCHUNK / 8);

    ull acc[MVROWS][5];
#pragma unroll
    for (int r = 0; r < MVROWS; r++)
#pragma unroll
        for (int p = 0; p < 5; p++) acc[r][p] = 0ull;

    for (int it = 0; it < KCHUNK / 256; it++) {
        int q = it * 32 + lane;
        uint4 a[MVROWS];
#pragma unroll
        for (int r = 0; r < MVROWS; r++) a[r] = Abase[r * rstride + q];
#pragma unroll
        for (int k8 = 0; k8 < 8; k8++) {
            ull h[5];
#pragma unroll
            for (int p = 0; p < 5; p++)
                h[p] = sh[(k8 * 5 + p) * (KCHUNK / 8) + q];
#pragma unroll
            for (int r = 0; r < MVROWS; r++) {
                unsigned w = (k8 < 2) ? a[r].x : (k8 < 4) ? a[r].y
                           : (k8 < 6) ? a[r].z : a[r].w;
                float av = (k8 & 1) ? __uint_as_float(w & 0xffff0000u)
                                    : __uint_as_float(w << 16);
                ull v = pack2(av, av);
#pragma unroll
                for (int p = 0; p < 5; p++) fma2(acc[r][p], v, h[p]);
            }
        }
    }

#pragma unroll
    for (int r = 0; r < MVROWS; r++) {
        float f[DD];
#pragma unroll
        for (int p = 0; p < 5; p++) unpack2(acc[r][p], f[2 * p], f[2 * p + 1]);
#pragma unroll
        for (int d = 0; d < DD; d++)
#pragma unroll
            for (int o = 16; o > 0; o >>= 1)
                f[d] += __shfl_down_sync(0xffffffffu, f[d], o);
        if (lane == 0)
#pragma unroll
            for (int d = 0; d < DD; d++) pout[(row0 + r) * DD + d] = f[d];
    }
}

// ---------------- CNN tile: 512 rows, 2 rows/thread -----------------------------
__device__ __forceinline__ void cnn_tile(char* smem_raw, int t, int layer,
                                         const float* Wc, const float* bc) {
    float* sIn = (float*)smem_raw;                      // (512+22)*11 floats
    ull*   sW  = (ull*)(smem_raw + 24000);              // 23*50 ull
    const int tid = threadIdx.x;
    const float* in = g_cnn[layer & 1];
    float*       o  = g_cnn[(layer & 1) ^ 1];
    const float* W  = Wc + layer * KS * KS;
    const float bias = bc[layer];

    for (int i = tid; i < KS * 50; i += NT) {
        int dl = i / 50, rem = i % 50, c = rem / 5, p = rem % 5;
        sW[i] = pack2(W[dl * KS + 11 + c - 2 * p], W[dl * KS + 11 + c - 2 * p - 1]);
    }
    int base = t * 512 - 11;
    for (int i = tid; i < (512 + 22) * DD; i += NT) {
        int rr = i / DD, c = i - rr * DD;
        int g = base + rr;
        sIn[rr * 11 + c] = (g >= 0 && g < L_WORDS) ? in[g * DD + c] : 0.f;
    }
    __syncthreads();

    ull b2 = pack2(bias, bias);
    ull acc[2][5];
#pragma unroll
    for (int r = 0; r < 2; r++)
#pragma unroll
        for (int p = 0; p < 5; p++) acc[r][p] = b2;
#pragma unroll 1
    for (int dl = 0; dl < KS; dl++) {
#pragma unroll
        for (int c = 0; c < DD; c++) {
            ull w[5];
#pragma unroll
            for (int p = 0; p < 5; p++) w[p] = sW[dl * 50 + c * 5 + p];
#pragma unroll
            for (int r = 0; r < 2; r++) {
                float xv = sIn[(tid + r * 256 + dl) * 11 + c];
                ull x2 = pack2(xv, xv);
#pragma unroll
                for (int p = 0; p < 5; p++) fma2(acc[r][p], x2, w[p]);
            }
        }
    }
#pragma unroll
    for (int r = 0; r < 2; r++) {
        int grow = t * 512 + tid + r * 256;
#pragma unroll
        for (int p = 0; p < 5; p++) {
            float v0, v1;
            unpack2(acc[r][p], v0, v1);
            o[grow * DD + 2 * p]     = fmaxf(v0, 0.f);
            o[grow * DD + 2 * p + 1] = fmaxf(v1, 0.f);
        }
    }
}

// ================== the one persistent kernel =================================
__global__ void __launch_bounds__(NT, 2) k_all(
    const int* __restrict__ fp, const float* __restrict__ A,
    const int* __restrict__ words, const float* __restrict__ embf,
    const float* __restrict__ embw,
    const float* __restrict__ Wg, const float* __restrict__ bg,
    const float* __restrict__ Wc, const float* __restrict__ bc,
    const float* __restrict__ Wat, const float* __restrict__ bat,
    const float* __restrict__ Wout, const float* __restrict__ bout,
    const float* __restrict__ Wint, const float* __restrict__ bint,
    float* __restrict__ out)
{
    extern __shared__ char smem_raw[];
    const int tid = threadIdx.x;
    const int bid = blockIdx.x;
    const int nb  = gridDim.x;
    const int gstride = nb * NT;

    // ---------- P0: gathers + hs layer0 ----------
    for (int m = bid * NT + tid; m < N_ATOMS; m += gstride) {
        float x[DD];
#pragma unroll
        for (int c = 0; c < DD; c++) {
            x[c] = embf[(size_t)fp[m] * DD + c];
            g_xs[m * DD + c] = x[c];
        }
        hs_store(m, x, Wg, bg);
    }
    for (int i = bid * NT + tid; i < L_WORDS * DD; i += gstride) {
        int n = i / DD, d = i - n * DD;
        g_cnn[0][i] = embw[(size_t)words[n] * DD + d];
    }
    gbar();

    // ---------- layer 0: 256 mv0 tiles (fp32->bf16) + 128 cnn L0 tiles ----------
    for (int u = bid; u < 384; u += nb) {
        if (u < 256) mv0_tile(smem_raw, u, A);
        else cnn_tile(smem_raw, u - 256, 0, Wc, bc);
        __syncthreads();
    }
    gbar();
    // xs += P; hs layer1
    for (int m = bid * NT + tid; m < N_ATOMS; m += gstride) {
        float x[DD];
#pragma unroll
        for (int c = 0; c < DD; c++) {
            float v = g_xs[m * DD + c] + g_pp[0][m * DD + c] + g_pp[1][m * DD + c];
            g_xs[m * DD + c] = v;
            x[c] = v;
        }
        hs_store(m, x, Wg + DD * DD, bg + DD);
    }
    gbar();

    // ---------- layers 1,2: 128 bf16 mv tiles + 128 cnn tiles ----------
    for (int layer = 1; layer < 3; layer++) {
        for (int u = bid; u < 256; u += nb) {
            if (u < 128) mv_tile(smem_raw, u);
            else cnn_tile(smem_raw, u - 128, layer, Wc, bc);
            __syncthreads();
        }
        gbar();
        if (layer == 1) {
            for (int m = bid * NT + tid; m < N_ATOMS; m += gstride) {
                float x[DD];
#pragma unroll
                for (int c = 0; c < DD; c++) {
                    float v = g_xs[m * DD + c] + g_pp[0][m * DD + c] + g_pp[1][m * DD + c];
                    g_xs[m * DD + c] = v;
                    x[c] = v;
                }
                hs_store(m, x, Wg + 2 * DD * DD, bg + 2 * DD);
            }
            gbar();
        }
    }

    // ---------- compound partials: grid-stride, per-block reduce ----------
    {
        float* red = (float*)smem_raw;
        float acc[DD];
#pragma unroll
        for (int d = 0; d < DD; d++) acc[d] = 0.f;
        for (int n = bid * NT + tid; n < N_ATOMS; n += gstride)
#pragma unroll
            for (int d = 0; d < DD; d++)
                acc[d] += g_xs[n * DD + d] + g_pp[0][n * DD + d] + g_pp[1][n * DD + d];
#pragma unroll
        for (int d = 0; d < DD; d++) red[tid * DD + d] = acc[d];
        __syncthreads();
        for (int s = 128; s > 0; s >>= 1) {
            if (tid < s) {
#pragma unroll
                for (int d = 0; d < DD; d++)
                    red[tid * DD + d] += red[(tid + s) * DD + d];
            }
            __syncthreads();
        }
        if (tid < DD) g_cpart[bid * DD + tid] = red[tid];
    }
    gbar();

    // ---------- redundant compound finalize + attention (all blocks) ----------
    {
        float* sWat = (float*)smem_raw;          // 100
        float* sbv  = sWat + DD * DD;            // 10
        float* shv  = sbv + DD;                  // 10
        float* red  = shv + DD + 2;              // 256*10
        if (tid < DD * DD) sWat[tid] = Wat[tid];
        if (tid < DD) {
            float s = 0.f;
            for (int b = 0; b < nb; b++) s += g_cpart[b * DD + tid];
            float comp = s * (1.f / N_ATOMS);
            if (bid == 0) g_comp[tid] = comp;
            sbv[tid] = bat[tid];
            red[tid] = comp;                     // stash comp for hv compute
        }
        __syncthreads();
        if (tid < DD) {
            float hv = sbv[tid];
#pragma unroll
            for (int c = 0; c < DD; c++) hv = fmaf(red[c], sWat[tid * DD + c], hv);
            shv[tid] = fmaxf(hv, 0.f);
        }
        __syncthreads();

        float acc[DD];
#pragma unroll
        for (int d = 0; d < DD; d++) acc[d] = 0.f;
        const float* in = g_cnn[1];   // after 3 conv layers: 0->1->0->1
        for (int l = bid * NT + tid; l < L_WORDS; l += gstride) {
            float x[DD];
#pragma unroll
            for (int c = 0; c < DD; c++) x[c] = in[l * DD + c];
            float hp[DD], wl = 0.f;
#pragma unroll
            for (int u = 0; u < DD; u++) {
                float v = sbv[u];
#pragma unroll
                for (int c = 0; c < DD; c++) v = fmaf(x[c], sWat[u * DD + c], v);
                v = fmaxf(v, 0.f);
                hp[u] = v;
                wl = fmaf(shv[u], v, wl);
            }
            wl = tanhf(wl);
#pragma unroll
            for (int d = 0; d < DD; d++) acc[d] = fmaf(wl, hp[d], acc[d]);
        }
        __syncthreads();
#pragma unroll
        for (int d = 0; d < DD; d++) red[tid * DD + d] = acc[d];
        __syncthreads();
        for (int s = 128; s > 0; s >>= 1) {
            if (tid < s) {
#pragma unroll
                for (int d = 0; d < DD; d++)
                    red[tid * DD + d] += red[(tid + s) * DD + d];
            }
            __syncthreads();
        }
        if (tid < DD) g_part[bid * DD + tid] = red[tid];
    }
    gbar();

    // ---------- final: reduce g_part + fusion MLP (block 0) ----------
    if (bid == 0) {
        float* red = (float*)smem_raw;
        float* cat = red + NT * DD;
        float acc[DD];
#pragma unroll
        for (int d = 0; d < DD; d++) acc[d] = 0.f;
        for (int b = tid; b < nb; b += NT)
#pragma unroll
            for (int d = 0; d < DD; d++) acc[d] += g_part[b * DD + d];
#pragma unroll
        for (int d = 0; d < DD; d++) red[tid * DD + d] = acc[d];
        __syncthreads();
        for (int s = 128; s > 0; s >>= 1) {
            if (tid < s) {
#pragma unroll
                for (int d = 0; d < DD; d++)
                    red[tid * DD + d] += red[(tid + s) * DD + d];
            }
            __syncthreads();
        }
        if (tid < DD) cat[tid] = g_comp[tid];
        if (tid >= DD && tid < 20) cat[tid] = red[tid - DD] * (1.f / L_WORDS);
        __syncthreads();
        if (tid < 32) {
            for (int j = 0; j < 3; j++) {
                float v = 0.f;
                if (tid < 20) {
                    v = bout[j * 20 + tid];
                    for (int c = 0; c < 20; c++)
                        v = fmaf(cat[c], Wout[j * 400 + tid * 20 + c], v);
                    v = fmaxf(v, 0.f);
                }
                __syncwarp();
                if (tid < 20) cat[tid] = v;
                __syncwarp();
            }
            if (tid < 2) {
                float v = bint[tid];
                for (int c = 0; c < 20; c++) v = fmaf(cat[c], Wint[tid * 20 + c], v);
                out[tid] = v;
            }
        }
    }
}

// ---------------- launch ------------------------------------------------------
extern "C" void kernel_launch(void* const* d_in, const int* in_sizes, int n_in,
                              void* d_out, int out_size) {
    const int*   fp    = (const int*)d_in[0];
    const float* A     = (const float*)d_in[1];
    const int*   words = (const int*)d_in[2];
    const float* embf  = (const float*)d_in[3];
    const float* embw  = (const float*)d_in[4];
    const float* Wg    = (const float*)d_in[5];
    const float* bg    = (const float*)d_in[6];
    const float* Wc    = (const float*)d_in[7];
    const float* bc    = (const float*)d_in[8];
    const float* Wat   = (const float*)d_in[9];
    const float* bat   = (const float*)d_in[10];
    const float* Wout  = (const float*)d_in[11];
    const float* bout  = (const float*)d_in[12];
    const float* Wint  = (const float*)d_in[13];
    const float* bint  = (const float*)d_in[14];
    float* out = (float*)d_out;

    cudaFuncSetAttribute(k_all, cudaFuncAttributeMaxDynamicSharedMemorySize, SMEM_BYTES);
    int dev = 0;
    cudaGetDevice(&dev);
    int nsm = 0;
    cudaDeviceGetAttribute(&nsm, cudaDevAttrMultiProcessorCount, dev);
    int per = 0;
    cudaOccupancyMaxActiveBlocksPerMultiprocessor(&per, k_all, NT, SMEM_BYTES);
    if (per < 1) per = 1;
    if (per > 2) per = 2;
    int grid = nsm * per;

    k_all<<<grid, NT, SMEM_BYTES>>>(fp, A, words, embf, embw, Wg, bg, Wc, bc,
                                    Wat, bat, Wout, bout, Wint, bint, out);
}